// round 6
// baseline (speedup 1.0000x reference)
#include <cuda_runtime.h>
#include <cuda_bf16.h>

#define NNODES 50000
#define NEDGES 800000
#define NB 4
#define NIN 32
#define H2 30

typedef unsigned long long ull;

// ---------------- device scratch ----------------
__device__ double g_stats[2];
__device__ float  g_norm[2];
__device__ int    g_is64;
__device__ int    g_src[NEDGES];
__device__ int    g_tgt[NEDGES];
__device__ __align__(16) __nv_bfloat16 g_Pb[NB * NNODES * 32];
__device__ __align__(16) __nv_bfloat16 g_Qb[NB * NNODES * 32];
__device__ __align__(16) float g_acc[NB * NNODES * 32];

__device__ __forceinline__ float sigm(float x) {
    return __fdividef(1.0f, 1.0f + __expf(-x));
}
__device__ __forceinline__ float sigm_fast(float x) {
    float t;
    asm("tanh.approx.f32 %0, %1;" : "=f"(t) : "f"(x * 0.5f));
    return fmaf(0.5f, t, 0.5f);
}
__device__ __forceinline__ ull pack2(float lo, float hi) {
    ull r;
    asm("mov.b64 %0, {%1,%2};" : "=l"(r) : "r"(__float_as_uint(lo)), "r"(__float_as_uint(hi)));
    return r;
}
__device__ __forceinline__ ull bcast2(float v) {
    ull r;
    asm("mov.b64 %0, {%1,%1};" : "=l"(r) : "r"(__float_as_uint(v)));
    return r;
}

// ---------------- 1. detect + zero stats ----------------
__global__ void k_detect(const int* __restrict__ ei) {
    int odd_or = 0;
    for (int k = 1; k < 128; k += 2) odd_or |= ei[k];
    g_is64 = (odd_or == 0) ? 1 : 0;
    g_stats[0] = 0.0;
    g_stats[1] = 0.0;
}

// ---------------- 2. convert indices ----------------
__global__ void k_convert(const int* __restrict__ ei) {
    int e = blockIdx.x * 256 + threadIdx.x;
    if (e >= NEDGES) return;
    int s, t;
    if (g_is64) {
        const long long* e64 = (const long long*)ei;
        s = (int)e64[e];
        t = (int)e64[NEDGES + e];
    } else {
        s = ei[e];
        t = ei[NEDGES + e];
    }
    s = min(max(s, 0), NNODES - 1);
    t = min(max(t, 0), NNODES - 1);
    g_src[e] = s;
    g_tgt[e] = t;
}

// ---------------- 3. reduce edge_attr (float4 + shuffle) ----------------
__global__ void k_reduce_ea(const float* __restrict__ ea) {
    __shared__ float s1[8], s2[8];
    float v1 = 0.0f, v2 = 0.0f;
    int stride = gridDim.x * 256;
    for (int i = blockIdx.x * 256 + threadIdx.x; i < NEDGES / 4; i += stride) {
        float4 v = ((const float4*)ea)[i];
        v1 += v.x + v.y + v.z + v.w;
        v2 += v.x * v.x + v.y * v.y + v.z * v.z + v.w * v.w;
    }
    #pragma unroll
    for (int o = 16; o > 0; o >>= 1) {
        v1 += __shfl_xor_sync(0xffffffffu, v1, o);
        v2 += __shfl_xor_sync(0xffffffffu, v2, o);
    }
    int w = threadIdx.x >> 5;
    if ((threadIdx.x & 31) == 0) { s1[w] = v1; s2[w] = v2; }
    __syncthreads();
    if (threadIdx.x == 0) {
        float t1 = 0.0f, t2 = 0.0f;
        #pragma unroll
        for (int i = 0; i < 8; i++) { t1 += s1[i]; t2 += s2[i]; }
        atomicAdd(&g_stats[0], (double)t1);
        atomicAdd(&g_stats[1], (double)t2);
    }
}

// ---------------- 4. finalize stats ----------------
__global__ void k_finalize_stats() {
    double s = g_stats[0], ss = g_stats[1];
    double n = (double)NEDGES;
    double mean = s / n;
    double var = (ss - s * s / n) / (n - 1.0);   // ddof=1
    g_norm[0] = (float)mean;
    g_norm[1] = (float)(1.0 / sqrt(var));
}

// ---------------- 5. precompute P/Q (bf16) + zero acc ----------------
__global__ void k_precompute(const float* __restrict__ x,
                             const float* __restrict__ W1,
                             const float* __restrict__ b1) {
    int tid = blockIdx.x * 256 + threadIdx.x;
    if (tid >= NB * NNODES * 32) return;
    int j   = tid & 31;
    int row = tid >> 5;
    const float* xr = x + (size_t)row * NIN;
    float p = 0.0f;
    float q = b1[j];
    #pragma unroll
    for (int i = 0; i < NIN; i++) {
        float xi = __ldg(&xr[i]);
        p = fmaf(xi, __ldg(&W1[i * 32 + j]), p);
        q = fmaf(xi, __ldg(&W1[(32 + i) * 32 + j]), q);
    }
    g_Pb[tid] = __float2bfloat16(p);
    g_Qb[tid] = __float2bfloat16(q);
    g_acc[tid] = 0.0f;
}

// ---------------- 6. edge kernel: 2 batches per thread ----------------
__global__ __launch_bounds__(128) void k_edge(const float* __restrict__ ea,
                                              const float* __restrict__ W1,
                                              const float* __restrict__ W2,
                                              const float* __restrict__ b2) {
    __shared__ __align__(16) ull sW2p[32 * 16];   // [j][m]: (W2[j][2m], W2[j][2m+1])
    __shared__ float sw1c[32];
    __shared__ ull   sb2p[16];

    for (int idx = threadIdx.x; idx < 512; idx += 128) {
        int j = idx >> 4, m = idx & 15;
        float w0 = (2 * m     < H2) ? W2[j * H2 + 2 * m]     : 0.0f;
        float w1 = (2 * m + 1 < H2) ? W2[j * H2 + 2 * m + 1] : 0.0f;
        sW2p[idx] = pack2(w0, w1);
    }
    if (threadIdx.x < 32) {
        sw1c[threadIdx.x] = W1[64 * 32 + threadIdx.x];
    }
    if (threadIdx.x < 16) {
        int m = threadIdx.x;
        float d0 = (2 * m     < H2) ? b2[2 * m]     : 0.0f;
        float d1 = (2 * m + 1 < H2) ? b2[2 * m + 1] : 0.0f;
        sb2p[m] = pack2(d0, d1);
    }
    __syncthreads();

    int e = blockIdx.x * 128 + threadIdx.x;
    if (e >= NEDGES) return;
    int b0 = blockIdx.y * 2;          // handles batches b0 and b0+1

    int src = g_src[e];
    int tgt = g_tgt[e];
    float ean = (ea[e] - g_norm[0]) * g_norm[1];

    // z1 for both batches
    float z1a[32], z1b[32];
    {
        const uint4* Pr = (const uint4*)(g_Pb + ((size_t)b0 * NNODES + src) * 32);
        const uint4* Qr = (const uint4*)(g_Qb + ((size_t)b0 * NNODES + tgt) * 32);
        uint4 pv[4], qv[4];
        #pragma unroll
        for (int m = 0; m < 4; m++) { pv[m] = Pr[m]; qv[m] = Qr[m]; }
        const __nv_bfloat162* pb = (const __nv_bfloat162*)pv;
        const __nv_bfloat162* qb = (const __nv_bfloat162*)qv;
        #pragma unroll
        for (int m = 0; m < 16; m++) {
            float2 pf = __bfloat1622float2(pb[m]);
            float2 qf = __bfloat1622float2(qb[m]);
            z1a[2 * m + 0] = pf.x + qf.x + ean * sw1c[2 * m + 0];
            z1a[2 * m + 1] = pf.y + qf.y + ean * sw1c[2 * m + 1];
        }
    }
    {
        const uint4* Pr = (const uint4*)(g_Pb + ((size_t)(b0 + 1) * NNODES + src) * 32);
        const uint4* Qr = (const uint4*)(g_Qb + ((size_t)(b0 + 1) * NNODES + tgt) * 32);
        uint4 pv[4], qv[4];
        #pragma unroll
        for (int m = 0; m < 4; m++) { pv[m] = Pr[m]; qv[m] = Qr[m]; }
        const __nv_bfloat162* pb = (const __nv_bfloat162*)pv;
        const __nv_bfloat162* qb = (const __nv_bfloat162*)qv;
        #pragma unroll
        for (int m = 0; m < 16; m++) {
            float2 pf = __bfloat1622float2(pb[m]);
            float2 qf = __bfloat1622float2(qb[m]);
            z1b[2 * m + 0] = pf.x + qf.x + ean * sw1c[2 * m + 0];
            z1b[2 * m + 1] = pf.y + qf.y + ean * sw1c[2 * m + 1];
        }
    }

    ull h0[16], h1[16];
    #pragma unroll
    for (int m = 0; m < 16; m++) { h0[m] = sb2p[m]; h1[m] = sb2p[m]; }

    #pragma unroll
    for (int j = 0; j < 32; j++) {
        ull ap0 = bcast2(sigm_fast(z1a[j]));
        ull ap1 = bcast2(sigm_fast(z1b[j]));
        const ulonglong2* wr = (const ulonglong2*)&sW2p[j * 16];
        #pragma unroll
        for (int m = 0; m < 8; m++) {
            ulonglong2 w = wr[m];                 // LDS.128 -> two 64b operands, no packing
            asm("fma.rn.f32x2 %0, %1, %2, %0;" : "+l"(h0[2 * m + 0]) : "l"(ap0), "l"(w.x));
            asm("fma.rn.f32x2 %0, %1, %2, %0;" : "+l"(h0[2 * m + 1]) : "l"(ap0), "l"(w.y));
            asm("fma.rn.f32x2 %0, %1, %2, %0;" : "+l"(h1[2 * m + 0]) : "l"(ap1), "l"(w.x));
            asm("fma.rn.f32x2 %0, %1, %2, %0;" : "+l"(h1[2 * m + 1]) : "l"(ap1), "l"(w.y));
        }
    }

    #pragma unroll
    for (int bb = 0; bb < 2; bb++) {
        const ull* hp = bb ? h1 : h0;
        float h2[32];
        #pragma unroll
        for (int m = 0; m < 16; m++) {
            unsigned lo, hi;
            asm("mov.b64 {%0,%1}, %2;" : "=r"(lo), "=r"(hi) : "l"(hp[m]));
            h2[2 * m + 0] = sigm_fast(__uint_as_float(lo));
            h2[2 * m + 1] = sigm_fast(__uint_as_float(hi));
        }
        h2[30] = 0.0f;   // pad channels must not scatter sigmoid(0)
        h2[31] = 0.0f;

        size_t base = (size_t)(b0 + bb) * NNODES;
        float4* at = (float4*)&g_acc[(base + tgt) * 32];
        float4* as = (float4*)&g_acc[(base + src) * 32];
        #pragma unroll
        for (int m = 0; m < 8; m++) {
            float4 hv = make_float4(h2[4 * m + 0], h2[4 * m + 1], h2[4 * m + 2], h2[4 * m + 3]);
            atomicAdd(at + m, hv);
            atomicAdd(as + m, make_float4(-hv.x, -hv.y, -hv.z, -hv.w));
        }
    }
}

// ---------------- 7. epilogue ----------------
__global__ void k_out(const float* __restrict__ W3,
                      const float* __restrict__ b3,
                      float* __restrict__ out) {
    int tid = blockIdx.x * 256 + threadIdx.x;
    if (tid >= NB * NNODES * 32) return;
    int j   = tid & 31;
    int row = tid >> 5;
    const float* ar = &g_acc[(size_t)row * 32];
    float o = b3[j];
    #pragma unroll
    for (int k = 0; k < H2; k++) {
        o = fmaf(ar[k], __ldg(&W3[k * 32 + j]), o);
    }
    out[tid] = sigm(o);
}

// ---------------- launch ----------------
extern "C" void kernel_launch(void* const* d_in, const int* in_sizes, int n_in,
                              void* d_out, int out_size) {
    const void* p_x = 0;  const void* p_ei = 0; const void* p_ea = 0;
    const void* p_W1 = 0; const void* p_b1 = 0; const void* p_W2 = 0;
    const void* p_b2 = 0; const void* p_W3 = 0; const void* p_b3 = 0;
    for (int i = 0; i < n_in; i++) {
        int s = in_sizes[i];
        const void* p = d_in[i];
        if      (s == NB * NNODES * NIN)  p_x = p;
        else if (s == 2 * NEDGES)         p_ei = p;
        else if (s == NEDGES)             p_ea = p;
        else if (s == (2 * NIN + 1) * 32) p_W1 = p;
        else if (s == 32 * H2)            { if (!p_W2) p_W2 = p; else p_W3 = p; }
        else if (s == 32)                 { if (!p_b1) p_b1 = p; else p_b3 = p; }
        else if (s == H2)                 p_b2 = p;
    }
    const float* x  = (const float*)p_x;
    const int*   ei = (const int*)p_ei;
    const float* ea = (const float*)p_ea;
    const float* W1 = (const float*)p_W1;
    const float* b1 = (const float*)p_b1;
    const float* W2 = (const float*)p_W2;
    const float* b2 = (const float*)p_b2;
    const float* W3 = (const float*)p_W3;
    const float* b3 = (const float*)p_b3;
    float* out = (float*)d_out;

    k_detect<<<1, 1>>>(ei);
    k_convert<<<(NEDGES + 255) / 256, 256>>>(ei);
    k_reduce_ea<<<296, 256>>>(ea);
    k_finalize_stats<<<1, 1>>>();
    k_precompute<<<(NB * NNODES * 32 + 255) / 256, 256>>>(x, W1, b1);
    dim3 egrid((NEDGES + 127) / 128, 2);
    k_edge<<<egrid, 128>>>(ea, W1, W2, b2);
    k_out<<<(NB * NNODES * 32 + 255) / 256, 256>>>(W3, b3, out);
}

// round 8
// speedup vs baseline: 1.4311x; 1.4311x over previous
#include <cuda_runtime.h>
#include <cuda_bf16.h>

#define NNODES 50000
#define NEDGES 800000
#define NB 4
#define NIN 32
#define H2 30

typedef unsigned long long ull;

// ---------------- device scratch ----------------
__device__ double g_stats[2];
__device__ float  g_norm[2];
__device__ int    g_is64;
__device__ int    g_src[NEDGES];
__device__ int    g_tgt[NEDGES];
__device__ __align__(16) __nv_bfloat16 g_Pb[NB * NNODES * 32];
__device__ __align__(16) __nv_bfloat16 g_Qb[NB * NNODES * 32];
__device__ __align__(16) float g_acc[NB * NNODES * 32];

__device__ __forceinline__ float sigm(float x) {
    return __fdividef(1.0f, 1.0f + __expf(-x));
}
__device__ __forceinline__ float sigm_fast(float x) {
    float t;
    asm("tanh.approx.f32 %0, %1;" : "=f"(t) : "f"(x * 0.5f));
    return fmaf(0.5f, t, 0.5f);
}
__device__ __forceinline__ ull pack2(float lo, float hi) {
    ull r;
    asm("mov.b64 %0, {%1,%2};" : "=l"(r) : "r"(__float_as_uint(lo)), "r"(__float_as_uint(hi)));
    return r;
}
__device__ __forceinline__ ull bcast2(float v) {
    ull r;
    asm("mov.b64 %0, {%1,%1};" : "=l"(r) : "r"(__float_as_uint(v)));
    return r;
}

// ---------------- 1. detect + zero stats ----------------
__global__ void k_detect(const int* __restrict__ ei) {
    int odd_or = 0;
    for (int k = 1; k < 128; k += 2) odd_or |= ei[k];
    g_is64 = (odd_or == 0) ? 1 : 0;
    g_stats[0] = 0.0;
    g_stats[1] = 0.0;
}

// ---------------- 2. convert indices ----------------
__global__ void k_convert(const int* __restrict__ ei) {
    int e = blockIdx.x * 256 + threadIdx.x;
    if (e >= NEDGES) return;
    int s, t;
    if (g_is64) {
        const long long* e64 = (const long long*)ei;
        s = (int)e64[e];
        t = (int)e64[NEDGES + e];
    } else {
        s = ei[e];
        t = ei[NEDGES + e];
    }
    s = min(max(s, 0), NNODES - 1);
    t = min(max(t, 0), NNODES - 1);
    g_src[e] = s;
    g_tgt[e] = t;
}

// ---------------- 3. reduce edge_attr (float4 + shuffle) ----------------
__global__ void k_reduce_ea(const float* __restrict__ ea) {
    __shared__ float s1[8], s2[8];
    float v1 = 0.0f, v2 = 0.0f;
    int stride = gridDim.x * 256;
    for (int i = blockIdx.x * 256 + threadIdx.x; i < NEDGES / 4; i += stride) {
        float4 v = ((const float4*)ea)[i];
        v1 += v.x + v.y + v.z + v.w;
        v2 += v.x * v.x + v.y * v.y + v.z * v.z + v.w * v.w;
    }
    #pragma unroll
    for (int o = 16; o > 0; o >>= 1) {
        v1 += __shfl_xor_sync(0xffffffffu, v1, o);
        v2 += __shfl_xor_sync(0xffffffffu, v2, o);
    }
    int w = threadIdx.x >> 5;
    if ((threadIdx.x & 31) == 0) { s1[w] = v1; s2[w] = v2; }
    __syncthreads();
    if (threadIdx.x == 0) {
        float t1 = 0.0f, t2 = 0.0f;
        #pragma unroll
        for (int i = 0; i < 8; i++) { t1 += s1[i]; t2 += s2[i]; }
        atomicAdd(&g_stats[0], (double)t1);
        atomicAdd(&g_stats[1], (double)t2);
    }
}

// ---------------- 4. finalize stats ----------------
__global__ void k_finalize_stats() {
    double s = g_stats[0], ss = g_stats[1];
    double n = (double)NEDGES;
    double mean = s / n;
    double var = (ss - s * s / n) / (n - 1.0);   // ddof=1
    g_norm[0] = (float)mean;
    g_norm[1] = (float)(1.0 / sqrt(var));
}

// ---------------- 5. precompute P/Q (bf16) + zero acc ----------------
__global__ void k_precompute(const float* __restrict__ x,
                             const float* __restrict__ W1,
                             const float* __restrict__ b1) {
    int tid = blockIdx.x * 256 + threadIdx.x;
    if (tid >= NB * NNODES * 32) return;
    int j   = tid & 31;
    int row = tid >> 5;
    const float* xr = x + (size_t)row * NIN;
    float p = 0.0f;
    float q = b1[j];
    #pragma unroll
    for (int i = 0; i < NIN; i++) {
        float xi = __ldg(&xr[i]);
        p = fmaf(xi, __ldg(&W1[i * 32 + j]), p);
        q = fmaf(xi, __ldg(&W1[(32 + i) * 32 + j]), q);
    }
    g_Pb[tid] = __float2bfloat16(p);
    g_Qb[tid] = __float2bfloat16(q);
    g_acc[tid] = 0.0f;
}

// ---------------- 6. edge kernel: 1 (edge,batch) per thread ----------------
__global__ __launch_bounds__(256) void k_edge(const float* __restrict__ ea,
                                              const float* __restrict__ W1,
                                              const float* __restrict__ W2,
                                              const float* __restrict__ b2) {
    __shared__ __align__(16) ull sW2p[32 * 16];   // [j][m]: (W2[j][2m], W2[j][2m+1])
    __shared__ float sw1c[32];
    __shared__ ull   sb2p[16];

    for (int idx = threadIdx.x; idx < 512; idx += 256) {
        int j = idx >> 4, m = idx & 15;
        float w0 = (2 * m     < H2) ? W2[j * H2 + 2 * m]     : 0.0f;
        float w1 = (2 * m + 1 < H2) ? W2[j * H2 + 2 * m + 1] : 0.0f;
        sW2p[idx] = pack2(w0, w1);
    }
    if (threadIdx.x < 32) {
        sw1c[threadIdx.x] = W1[64 * 32 + threadIdx.x];
    }
    if (threadIdx.x < 16) {
        int m = threadIdx.x;
        float d0 = (2 * m     < H2) ? b2[2 * m]     : 0.0f;
        float d1 = (2 * m + 1 < H2) ? b2[2 * m + 1] : 0.0f;
        sb2p[m] = pack2(d0, d1);
    }
    __syncthreads();

    int e = blockIdx.x * 256 + threadIdx.x;
    if (e >= NEDGES) return;
    int b = blockIdx.y;

    int src = g_src[e];
    int tgt = g_tgt[e];
    float ean = (ea[e] - g_norm[0]) * g_norm[1];

    const uint4* Pr = (const uint4*)(g_Pb + ((size_t)b * NNODES + src) * 32);
    const uint4* Qr = (const uint4*)(g_Qb + ((size_t)b * NNODES + tgt) * 32);
    uint4 pv[4], qv[4];
    #pragma unroll
    for (int m = 0; m < 4; m++) { pv[m] = Pr[m]; qv[m] = Qr[m]; }

    const __nv_bfloat162* pb = (const __nv_bfloat162*)pv;
    const __nv_bfloat162* qb = (const __nv_bfloat162*)qv;

    float z1[32];
    #pragma unroll
    for (int m = 0; m < 16; m++) {
        float2 pf = __bfloat1622float2(pb[m]);
        float2 qf = __bfloat1622float2(qb[m]);
        z1[2 * m + 0] = pf.x + qf.x + ean * sw1c[2 * m + 0];
        z1[2 * m + 1] = pf.y + qf.y + ean * sw1c[2 * m + 1];
    }

    ull h2p[16];
    #pragma unroll
    for (int m = 0; m < 16; m++) h2p[m] = sb2p[m];

    #pragma unroll
    for (int j = 0; j < 32; j++) {
        ull ap = bcast2(sigm_fast(z1[j]));
        const ulonglong2* wr = (const ulonglong2*)&sW2p[j * 16];
        #pragma unroll
        for (int m = 0; m < 8; m++) {
            ulonglong2 w = wr[m];                 // LDS.128 -> two ready 64b operands
            asm("fma.rn.f32x2 %0, %1, %2, %0;" : "+l"(h2p[2 * m + 0]) : "l"(ap), "l"(w.x));
            asm("fma.rn.f32x2 %0, %1, %2, %0;" : "+l"(h2p[2 * m + 1]) : "l"(ap), "l"(w.y));
        }
    }

    float h2[32];
    #pragma unroll
    for (int m = 0; m < 16; m++) {
        unsigned lo, hi;
        asm("mov.b64 {%0,%1}, %2;" : "=r"(lo), "=r"(hi) : "l"(h2p[m]));
        h2[2 * m + 0] = sigm_fast(__uint_as_float(lo));
        h2[2 * m + 1] = sigm_fast(__uint_as_float(hi));
    }
    h2[30] = 0.0f;   // pad channels must not scatter sigmoid(0)
    h2[31] = 0.0f;

    float4* at = (float4*)&g_acc[((size_t)b * NNODES + tgt) * 32];
    float4* as = (float4*)&g_acc[((size_t)b * NNODES + src) * 32];
    #pragma unroll
    for (int m = 0; m < 8; m++) {
        float4 hv = make_float4(h2[4 * m + 0], h2[4 * m + 1], h2[4 * m + 2], h2[4 * m + 3]);
        atomicAdd(at + m, hv);
        atomicAdd(as + m, make_float4(-hv.x, -hv.y, -hv.z, -hv.w));
    }
}

// ---------------- 7. epilogue ----------------
__global__ void k_out(const float* __restrict__ W3,
                      const float* __restrict__ b3,
                      float* __restrict__ out) {
    int tid = blockIdx.x * 256 + threadIdx.x;
    if (tid >= NB * NNODES * 32) return;
    int j   = tid & 31;
    int row = tid >> 5;
    const float* ar = &g_acc[(size_t)row * 32];
    float o = b3[j];
    #pragma unroll
    for (int k = 0; k < H2; k++) {
        o = fmaf(ar[k], __ldg(&W3[k * 32 + j]), o);
    }
    out[tid] = sigm(o);
}

// ---------------- launch ----------------
extern "C" void kernel_launch(void* const* d_in, const int* in_sizes, int n_in,
                              void* d_out, int out_size) {
    const void* p_x = 0;  const void* p_ei = 0; const void* p_ea = 0;
    const void* p_W1 = 0; const void* p_b1 = 0; const void* p_W2 = 0;
    const void* p_b2 = 0; const void* p_W3 = 0; const void* p_b3 = 0;
    for (int i = 0; i < n_in; i++) {
        int s = in_sizes[i];
        const void* p = d_in[i];
        if      (s == NB * NNODES * NIN)  p_x = p;
        else if (s == 2 * NEDGES)         p_ei = p;
        else if (s == NEDGES)             p_ea = p;
        else if (s == (2 * NIN + 1) * 32) p_W1 = p;
        else if (s == 32 * H2)            { if (!p_W2) p_W2 = p; else p_W3 = p; }
        else if (s == 32)                 { if (!p_b1) p_b1 = p; else p_b3 = p; }
        else if (s == H2)                 p_b2 = p;
    }
    const float* x  = (const float*)p_x;
    const int*   ei = (const int*)p_ei;
    const float* ea = (const float*)p_ea;
    const float* W1 = (const float*)p_W1;
    const float* b1 = (const float*)p_b1;
    const float* W2 = (const float*)p_W2;
    const float* b2 = (const float*)p_b2;
    const float* W3 = (const float*)p_W3;
    const float* b3 = (const float*)p_b3;
    float* out = (float*)d_out;

    k_detect<<<1, 1>>>(ei);
    k_convert<<<(NEDGES + 255) / 256, 256>>>(ei);
    k_reduce_ea<<<296, 256>>>(ea);
    k_finalize_stats<<<1, 1>>>();
    k_precompute<<<(NB * NNODES * 32 + 255) / 256, 256>>>(x, W1, b1);
    dim3 egrid((NEDGES + 255) / 256, NB);
    k_edge<<<egrid, 256>>>(ea, W1, W2, b2);
    k_out<<<(NB * NNODES * 32 + 255) / 256, 256>>>(W3, b3, out);
}

// round 9
// speedup vs baseline: 1.4510x; 1.0140x over previous
#include <cuda_runtime.h>
#include <cuda_bf16.h>

#define NNODES 50000
#define NEDGES 800000
#define NB 4
#define NIN 32
#define H2 30
#define KPER 4

typedef unsigned long long ull;

// ---------------- device scratch ----------------
__device__ double g_stats[2];
__device__ float  g_norm[2];
__device__ int    g_is64;
__device__ int    g_src[NEDGES];
__device__ int    g_tgt[NEDGES];
__device__ int    g_hist[NNODES];
__device__ int    g_cur[NNODES];
__device__ int    g_ssrc[NEDGES];          // tgt-sorted
__device__ int    g_stgt[NEDGES];
__device__ float  g_sea[NEDGES];           // normalized ea, tgt-sorted
__device__ __align__(16) __nv_bfloat16 g_Pb[NB * NNODES * 32];
__device__ __align__(16) __nv_bfloat16 g_Qb[NB * NNODES * 32];
__device__ __align__(16) float g_acc[NB * NNODES * 32];

__device__ __forceinline__ float sigm(float x) {
    return __fdividef(1.0f, 1.0f + __expf(-x));
}
__device__ __forceinline__ float sigm_fast(float x) {
    float t;
    asm("tanh.approx.f32 %0, %1;" : "=f"(t) : "f"(x * 0.5f));
    return fmaf(0.5f, t, 0.5f);
}
__device__ __forceinline__ ull pack2(float lo, float hi) {
    ull r;
    asm("mov.b64 %0, {%1,%2};" : "=l"(r) : "r"(__float_as_uint(lo)), "r"(__float_as_uint(hi)));
    return r;
}
__device__ __forceinline__ ull bcast2(float v) {
    ull r;
    asm("mov.b64 %0, {%1,%1};" : "=l"(r) : "r"(__float_as_uint(v)));
    return r;
}

// ---------------- 1. detect dtype + zero hist/stats ----------------
__global__ void k_detect(const int* __restrict__ ei) {
    int tid = blockIdx.x * 256 + threadIdx.x;
    if (tid < NNODES) g_hist[tid] = 0;
    if (tid == 0) {
        int odd_or = 0;
        for (int k = 1; k < 128; k += 2) odd_or |= ei[k];
        g_is64 = (odd_or == 0) ? 1 : 0;
        g_stats[0] = 0.0;
        g_stats[1] = 0.0;
    }
}

// ---------------- 2. convert + histogram + ea reduce ----------------
__global__ void k_convert(const int* __restrict__ ei, const float* __restrict__ ea) {
    __shared__ float s1[8], s2[8];
    int e = blockIdx.x * 256 + threadIdx.x;     // grid covers exactly NEDGES
    int s, t;
    if (g_is64) {
        const long long* e64 = (const long long*)ei;
        s = (int)e64[e];
        t = (int)e64[NEDGES + e];
    } else {
        s = ei[e];
        t = ei[NEDGES + e];
    }
    s = min(max(s, 0), NNODES - 1);
    t = min(max(t, 0), NNODES - 1);
    g_src[e] = s;
    g_tgt[e] = t;
    atomicAdd(&g_hist[t], 1);

    float v = ea[e];
    float v1 = v, v2 = v * v;
    #pragma unroll
    for (int o = 16; o > 0; o >>= 1) {
        v1 += __shfl_xor_sync(0xffffffffu, v1, o);
        v2 += __shfl_xor_sync(0xffffffffu, v2, o);
    }
    int w = threadIdx.x >> 5;
    if ((threadIdx.x & 31) == 0) { s1[w] = v1; s2[w] = v2; }
    __syncthreads();
    if (threadIdx.x == 0) {
        float t1 = 0.0f, t2 = 0.0f;
        #pragma unroll
        for (int i = 0; i < 8; i++) { t1 += s1[i]; t2 += s2[i]; }
        atomicAdd(&g_stats[0], (double)t1);
        atomicAdd(&g_stats[1], (double)t2);
    }
}

// ---------------- 3. scan hist -> offsets; finalize norm ----------------
__global__ void k_scan() {
    __shared__ int part[1024];
    const int CH = (NNODES + 1023) / 1024;      // 49
    int tid = threadIdx.x;
    int base = tid * CH;
    int s = 0;
    for (int i = 0; i < CH; i++)
        if (base + i < NNODES) s += g_hist[base + i];
    part[tid] = s;
    __syncthreads();
    for (int off = 1; off < 1024; off <<= 1) {
        int v = (tid >= off) ? part[tid - off] : 0;
        __syncthreads();
        part[tid] += v;
        __syncthreads();
    }
    int run = part[tid] - s;                    // exclusive base
    for (int i = 0; i < CH; i++) {
        if (base + i < NNODES) {
            g_cur[base + i] = run;
            run += g_hist[base + i];
        }
    }
    if (tid == 0) {
        double su = g_stats[0], ss = g_stats[1];
        double n = (double)NEDGES;
        double mean = su / n;
        double var = (ss - su * su / n) / (n - 1.0);   // ddof=1
        g_norm[0] = (float)mean;
        g_norm[1] = (float)(1.0 / sqrt(var));
    }
}

// ---------------- 4. scatter into tgt-sorted order ----------------
__global__ void k_scatter(const float* __restrict__ ea) {
    int e = blockIdx.x * 256 + threadIdx.x;
    if (e >= NEDGES) return;
    int t = g_tgt[e];
    int pos = atomicAdd(&g_cur[t], 1);
    g_ssrc[pos] = g_src[e];
    g_stgt[pos] = t;
    g_sea[pos]  = (ea[e] - g_norm[0]) * g_norm[1];
}

// ---------------- 5. precompute P/Q (bf16) + zero acc ----------------
__global__ void k_precompute(const float* __restrict__ x,
                             const float* __restrict__ W1,
                             const float* __restrict__ b1) {
    int tid = blockIdx.x * 256 + threadIdx.x;
    if (tid >= NB * NNODES * 32) return;
    int j   = tid & 31;
    int row = tid >> 5;
    const float* xr = x + (size_t)row * NIN;
    float p = 0.0f;
    float q = b1[j];
    #pragma unroll
    for (int i = 0; i < NIN; i++) {
        float xi = __ldg(&xr[i]);
        p = fmaf(xi, __ldg(&W1[i * 32 + j]), p);
        q = fmaf(xi, __ldg(&W1[(32 + i) * 32 + j]), q);
    }
    g_Pb[tid] = __float2bfloat16(p);
    g_Qb[tid] = __float2bfloat16(q);
    g_acc[tid] = 0.0f;
}

// ---------------- 6. edge kernel: KPER sorted edges/thread, run-aggregated add-side ----------------
__global__ __launch_bounds__(128, 3) void k_edge(const float* __restrict__ W1,
                                                 const float* __restrict__ W2,
                                                 const float* __restrict__ b2) {
    __shared__ __align__(16) ull sW2p[32 * 16];
    __shared__ float sw1c[32];
    __shared__ ull   sb2p[16];

    for (int idx = threadIdx.x; idx < 512; idx += 128) {
        int j = idx >> 4, m = idx & 15;
        float w0 = (2 * m     < H2) ? W2[j * H2 + 2 * m]     : 0.0f;
        float w1 = (2 * m + 1 < H2) ? W2[j * H2 + 2 * m + 1] : 0.0f;
        sW2p[idx] = pack2(w0, w1);
    }
    if (threadIdx.x < 32) {
        sw1c[threadIdx.x] = W1[64 * 32 + threadIdx.x];
    }
    if (threadIdx.x < 16) {
        int m = threadIdx.x;
        float d0 = (2 * m     < H2) ? b2[2 * m]     : 0.0f;
        float d1 = (2 * m + 1 < H2) ? b2[2 * m + 1] : 0.0f;
        sb2p[m] = pack2(d0, d1);
    }
    __syncthreads();

    int base_e = (blockIdx.x * 128 + threadIdx.x) * KPER;
    int b = blockIdx.y;
    size_t bbase = (size_t)b * NNODES;

    float4 acc[8];
    int cur = -1;

    for (int k = 0; k < KPER; k++) {
        int e = base_e + k;
        if (e >= NEDGES) break;

        int src = g_ssrc[e];
        int tgt = g_stgt[e];
        float ean = g_sea[e];

        const uint4* Pr = (const uint4*)(g_Pb + (bbase + src) * 32);
        const uint4* Qr = (const uint4*)(g_Qb + (bbase + tgt) * 32);
        uint4 pv[4], qv[4];
        #pragma unroll
        for (int m = 0; m < 4; m++) { pv[m] = Pr[m]; qv[m] = Qr[m]; }

        const __nv_bfloat162* pb = (const __nv_bfloat162*)pv;
        const __nv_bfloat162* qb = (const __nv_bfloat162*)qv;

        float z1[32];
        #pragma unroll
        for (int m = 0; m < 16; m++) {
            float2 pf = __bfloat1622float2(pb[m]);
            float2 qf = __bfloat1622float2(qb[m]);
            z1[2 * m + 0] = pf.x + qf.x + ean * sw1c[2 * m + 0];
            z1[2 * m + 1] = pf.y + qf.y + ean * sw1c[2 * m + 1];
        }

        ull h2p[16];
        #pragma unroll
        for (int m = 0; m < 16; m++) h2p[m] = sb2p[m];

        #pragma unroll
        for (int j = 0; j < 32; j++) {
            ull ap = bcast2(sigm_fast(z1[j]));
            const ulonglong2* wr = (const ulonglong2*)&sW2p[j * 16];
            #pragma unroll
            for (int m = 0; m < 8; m++) {
                ulonglong2 w = wr[m];
                asm("fma.rn.f32x2 %0, %1, %2, %0;" : "+l"(h2p[2 * m + 0]) : "l"(ap), "l"(w.x));
                asm("fma.rn.f32x2 %0, %1, %2, %0;" : "+l"(h2p[2 * m + 1]) : "l"(ap), "l"(w.y));
            }
        }

        float h2[32];
        #pragma unroll
        for (int m = 0; m < 16; m++) {
            unsigned lo, hi;
            asm("mov.b64 {%0,%1}, %2;" : "=r"(lo), "=r"(hi) : "l"(h2p[m]));
            h2[2 * m + 0] = sigm_fast(__uint_as_float(lo));
            h2[2 * m + 1] = sigm_fast(__uint_as_float(hi));
        }
        h2[30] = 0.0f;   // pad channels must not scatter sigmoid(0)
        h2[31] = 0.0f;

        // sub-side: immediate REDs to src (random)
        float4* as = (float4*)&g_acc[(bbase + src) * 32];
        #pragma unroll
        for (int m = 0; m < 8; m++) {
            atomicAdd(as + m, make_float4(-h2[4 * m + 0], -h2[4 * m + 1],
                                          -h2[4 * m + 2], -h2[4 * m + 3]));
        }

        // add-side: register-aggregate runs of equal tgt
        if (tgt != cur) {
            if (cur >= 0) {
                float4* at = (float4*)&g_acc[(bbase + cur) * 32];
                #pragma unroll
                for (int m = 0; m < 8; m++) atomicAdd(at + m, acc[m]);
            }
            cur = tgt;
            #pragma unroll
            for (int m = 0; m < 8; m++)
                acc[m] = make_float4(h2[4 * m + 0], h2[4 * m + 1], h2[4 * m + 2], h2[4 * m + 3]);
        } else {
            #pragma unroll
            for (int m = 0; m < 8; m++) {
                acc[m].x += h2[4 * m + 0];
                acc[m].y += h2[4 * m + 1];
                acc[m].z += h2[4 * m + 2];
                acc[m].w += h2[4 * m + 3];
            }
        }
    }

    if (cur >= 0) {
        float4* at = (float4*)&g_acc[(bbase + cur) * 32];
        #pragma unroll
        for (int m = 0; m < 8; m++) atomicAdd(at + m, acc[m]);
    }
}

// ---------------- 7. epilogue ----------------
__global__ void k_out(const float* __restrict__ W3,
                      const float* __restrict__ b3,
                      float* __restrict__ out) {
    int tid = blockIdx.x * 256 + threadIdx.x;
    if (tid >= NB * NNODES * 32) return;
    int j   = tid & 31;
    int row = tid >> 5;
    const float* ar = &g_acc[(size_t)row * 32];
    float o = b3[j];
    #pragma unroll
    for (int k = 0; k < H2; k++) {
        o = fmaf(ar[k], __ldg(&W3[k * 32 + j]), o);
    }
    out[tid] = sigm(o);
}

// ---------------- launch ----------------
extern "C" void kernel_launch(void* const* d_in, const int* in_sizes, int n_in,
                              void* d_out, int out_size) {
    const void* p_x = 0;  const void* p_ei = 0; const void* p_ea = 0;
    const void* p_W1 = 0; const void* p_b1 = 0; const void* p_W2 = 0;
    const void* p_b2 = 0; const void* p_W3 = 0; const void* p_b3 = 0;
    for (int i = 0; i < n_in; i++) {
        int s = in_sizes[i];
        const void* p = d_in[i];
        if      (s == NB * NNODES * NIN)  p_x = p;
        else if (s == 2 * NEDGES)         p_ei = p;
        else if (s == NEDGES)             p_ea = p;
        else if (s == (2 * NIN + 1) * 32) p_W1 = p;
        else if (s == 32 * H2)            { if (!p_W2) p_W2 = p; else p_W3 = p; }
        else if (s == 32)                 { if (!p_b1) p_b1 = p; else p_b3 = p; }
        else if (s == H2)                 p_b2 = p;
    }
    const float* x  = (const float*)p_x;
    const int*   ei = (const int*)p_ei;
    const float* ea = (const float*)p_ea;
    const float* W1 = (const float*)p_W1;
    const float* b1 = (const float*)p_b1;
    const float* W2 = (const float*)p_W2;
    const float* b2 = (const float*)p_b2;
    const float* W3 = (const float*)p_W3;
    const float* b3 = (const float*)p_b3;
    float* out = (float*)d_out;

    k_detect<<<(NNODES + 255) / 256, 256>>>(ei);
    k_convert<<<NEDGES / 256, 256>>>(ei, ea);
    k_scan<<<1, 1024>>>();
    k_scatter<<<(NEDGES + 255) / 256, 256>>>(ea);
    k_precompute<<<(NB * NNODES * 32 + 255) / 256, 256>>>(x, W1, b1);
    dim3 egrid((NEDGES + 128 * KPER - 1) / (128 * KPER), NB);
    k_edge<<<egrid, 128>>>(W1, W2, b2);
    k_out<<<(NB * NNODES * 32 + 255) / 256, 256>>>(W3, b3, out);
}